// round 14
// baseline (speedup 1.0000x reference)
#include <cuda_runtime.h>
#include <cuda_fp16.h>
#include <cstdint>

// ----------------------------------------------------------------------------
// WQLinearGEMM: out[M,N] = x[M,K] @ dequant(qweight,qzeros,scales)[K,N] + bias
// Round 12: R10 base (384 thr, 12 warps 2Mx6N, warp tile 64x64, BK=64, STG=3)
// + per-warp ks rotation to desynchronize LDSM/MMA bursts across warps.
// Fused prepass unchanged.
// ----------------------------------------------------------------------------

#define BM 128
#define BN 384
#define BK 64
#define STG 3
#define AST 72    // A smem row stride (halves): banks step 4/row, conflict-free
#define BST 392   // B smem row stride (halves): banks step 4/row, conflict-free

// static scratch: x fp16 (64MB), W fp16 (96MB)
static __device__ __half g_xh[8192UL * 4096UL];
static __device__ __half g_wdeq[4096UL * 12288UL];

// ------------------------------ helpers -------------------------------------
__device__ __forceinline__ uint32_t smem_u32(const void* p) {
    return (uint32_t)__cvta_generic_to_shared(p);
}
__device__ __forceinline__ void cpa16(uint32_t dst, const void* src) {
    asm volatile("cp.async.cg.shared.global [%0], [%1], 16;\n" :: "r"(dst), "l"(src));
}
__device__ __forceinline__ void cp_commit() {
    asm volatile("cp.async.commit_group;\n");
}
template <int NREM>
__device__ __forceinline__ void cp_wait() {
    asm volatile("cp.async.wait_group %0;\n" :: "n"(NREM));
}
__device__ __forceinline__ void st_cs_v4(void* p, uint4 v) {
    asm volatile("st.global.cs.v4.u32 [%0], {%1,%2,%3,%4};"
                 :: "l"(p), "r"(v.x), "r"(v.y), "r"(v.z), "r"(v.w) : "memory");
}

// ------------------- fused prepass: x f32->f16 + dequant ---------------------
__global__ void prep_kernel(const float* __restrict__ x, long long xcnt8,
                            const int* __restrict__ qw,
                            const int* __restrict__ qz,
                            const float* __restrict__ scales,
                            int K, int N, int xb) {
    if ((int)blockIdx.x < xb) {
        long long i = (long long)blockIdx.x * blockDim.x + threadIdx.x;
        if (i >= xcnt8) return;
        const float4* src = reinterpret_cast<const float4*>(x) + i * 2;
        float4 v0 = src[0];
        float4 v1 = src[1];
        __half2 a = __floats2half2_rn(v0.x, v0.y);
        __half2 b = __floats2half2_rn(v0.z, v0.w);
        __half2 c = __floats2half2_rn(v1.x, v1.y);
        __half2 d = __floats2half2_rn(v1.z, v1.w);
        uint4 u;
        u.x = *reinterpret_cast<const uint32_t*>(&a);
        u.y = *reinterpret_cast<const uint32_t*>(&b);
        u.z = *reinterpret_cast<const uint32_t*>(&c);
        u.w = *reinterpret_cast<const uint32_t*>(&d);
        st_cs_v4(reinterpret_cast<uint4*>(g_xh) + i, u);
    } else {
        const int N8 = N >> 3;
        long long idx = (long long)(blockIdx.x - xb) * blockDim.x + threadIdx.x;
        if (idx >= (long long)K * N8) return;
        int k  = (int)(idx / N8);
        int n8 = (int)(idx - (long long)k * N8);
        int g  = k >> 7;  // GROUP_SIZE = 128

        unsigned u = (unsigned)qw[idx];
        unsigned z = (unsigned)qz[(size_t)g * N8 + n8];
        float4 s0 = *reinterpret_cast<const float4*>(scales + (size_t)g * N + n8 * 8);
        float4 s1 = *reinterpret_cast<const float4*>(scales + (size_t)g * N + n8 * 8 + 4);
        float s[8] = {s0.x, s0.y, s0.z, s0.w, s1.x, s1.y, s1.z, s1.w};

        __half outv[8];
#pragma unroll
        for (int j = 0; j < 8; ++j) {
            // output element j comes from nibble {0,4,1,5,2,6,3,7}[j]
            const int sh = (j & 1) ? (16 + (j >> 1) * 4) : ((j >> 1) * 4);
            int wq = (u >> sh) & 15;
            int zq = (z >> sh) & 15;
            outv[j] = __float2half_rn((float)(wq - zq) * s[j]);
        }
        st_cs_v4(g_wdeq + (size_t)k * N + n8 * 8,
                 *reinterpret_cast<const uint4*>(outv));
    }
}

// ------------------------------- GEMM kernel --------------------------------
// 384 threads, 12 warps (2M x 6N), warp tile 64x64 via m16n8k16.
// Per-warp ks rotation desynchronizes fragment-load bursts across warps.
__global__ __launch_bounds__(384, 1)
void gemm_hmma(const float* __restrict__ bias, float* __restrict__ C,
               int M, int N, int K) {
    extern __shared__ __half sm[];
    __half* As = sm;                       // [STG][BM][AST]
    __half* Bs = sm + STG * BM * AST;      // [STG][BK][BST]

    const int tid  = threadIdx.x;
    const int lane = tid & 31;
    const int warp = tid >> 5;
    const int wm = warp / 6;   // 0..1
    const int wn = warp % 6;   // 0..5

    const int bm = blockIdx.y * BM;
    const int bn = blockIdx.x * BN;
    const int KT = K / BK;

    const __half* Ag = g_xh   + (size_t)bm * K;
    const __half* Bg = g_wdeq + (size_t)bn;

    float acc[4][8][4];
#pragma unroll
    for (int i = 0; i < 4; ++i)
#pragma unroll
        for (int j = 0; j < 8; ++j)
#pragma unroll
            for (int r = 0; r < 4; ++r) acc[i][j][r] = 0.0f;

    // cp.async coords: A handled by threads 0..255 (4 chunks), B by all (8 chunks)
    const int ar = tid >> 3;            // A row (0..31 for tid<256), +32*it
    const int ac = (tid & 7) * 8;       // A col
    const int br = tid / 48;            // B row (0..7), +8*it
    const int bc = (tid % 48) * 8;      // B col (0..376)

    auto load_stage = [&](int s, int kt) {
        if (tid < 256) {
            const __half* Asrc = Ag + kt * BK;
            uint32_t ad = smem_u32(As + s * BM * AST);
#pragma unroll
            for (int it = 0; it < 4; ++it) {
                int r = ar + it * 32;
                cpa16(ad + (r * AST + ac) * 2, Asrc + (size_t)r * K + ac);
            }
        }
        const __half* Bsrc = Bg + (size_t)(kt * BK) * N;
        uint32_t bd = smem_u32(Bs + s * BK * BST);
#pragma unroll
        for (int it = 0; it < 8; ++it) {
            int r = br + it * 8;
            cpa16(bd + (r * BST + bc) * 2, Bsrc + (size_t)r * N + bc);
        }
    };

    // fragment ldmatrix coords (hoisted)
    const int a_row_base = wm * 64 + (lane & 15);
    const int a_col_lane = (lane >> 4) * 8;
    const int b_row_lane = lane & 15;
    const int b_col_base = wn * 64 + (lane >> 4) * 8;
    const int ks_rot = warp & 3;   // per-warp rotation of k-slice order

    // prologue: stages 0..STG-2
#pragma unroll
    for (int p = 0; p < STG - 1; ++p) {
        load_stage(p, p);
        cp_commit();
    }

#pragma unroll 1
    for (int kt = 0; kt < KT; ++kt) {
        cp_wait<STG - 2>();
        __syncthreads();
        int nk = kt + STG - 1;
        if (nk < KT) load_stage(nk % STG, nk);
        cp_commit();

        const int s = kt % STG;
        uint32_t abase = smem_u32(As + s * BM * AST);
        uint32_t bbase = smem_u32(Bs + s * BK * BST);

#pragma unroll
        for (int kk = 0; kk < BK / 16; ++kk) {
            const int ks = (kk + ks_rot) & 3;   // staggered slice order per warp
            uint32_t a[4][4];
            uint32_t b[4][4];
#pragma unroll
            for (int i = 0; i < 4; ++i) {
                int row = a_row_base + i * 16;
                int col = ks * 16 + a_col_lane;
                asm volatile(
                    "ldmatrix.sync.aligned.m8n8.x4.shared.b16 {%0,%1,%2,%3}, [%4];"
                    : "=r"(a[i][0]), "=r"(a[i][1]), "=r"(a[i][2]), "=r"(a[i][3])
                    : "r"(abase + (row * AST + col) * 2));
            }
#pragma unroll
            for (int jj = 0; jj < 4; ++jj) {
                int row = ks * 16 + b_row_lane;
                int col = b_col_base + jj * 16;
                asm volatile(
                    "ldmatrix.sync.aligned.m8n8.x4.trans.shared.b16 {%0,%1,%2,%3}, [%4];"
                    : "=r"(b[jj][0]), "=r"(b[jj][1]), "=r"(b[jj][2]), "=r"(b[jj][3])
                    : "r"(bbase + (row * BST + col) * 2));
            }
#pragma unroll
            for (int i = 0; i < 4; ++i)
#pragma unroll
                for (int jj = 0; jj < 4; ++jj) {
                    asm volatile(
                        "mma.sync.aligned.m16n8k16.row.col.f32.f16.f16.f32 "
                        "{%0,%1,%2,%3}, {%4,%5,%6,%7}, {%8,%9}, {%0,%1,%2,%3};"
                        : "+f"(acc[i][jj * 2][0]), "+f"(acc[i][jj * 2][1]),
                          "+f"(acc[i][jj * 2][2]), "+f"(acc[i][jj * 2][3])
                        : "r"(a[i][0]), "r"(a[i][1]), "r"(a[i][2]), "r"(a[i][3]),
                          "r"(b[jj][0]), "r"(b[jj][1]));
                    asm volatile(
                        "mma.sync.aligned.m16n8k16.row.col.f32.f16.f16.f32 "
                        "{%0,%1,%2,%3}, {%4,%5,%6,%7}, {%8,%9}, {%0,%1,%2,%3};"
                        : "+f"(acc[i][jj * 2 + 1][0]), "+f"(acc[i][jj * 2 + 1][1]),
                          "+f"(acc[i][jj * 2 + 1][2]), "+f"(acc[i][jj * 2 + 1][3])
                        : "r"(a[i][0]), "r"(a[i][1]), "r"(a[i][2]), "r"(a[i][3]),
                          "r"(b[jj][2]), "r"(b[jj][3]));
                }
        }
    }

    // epilogue: round acc to f16, add f16 bias, widen to f32 (matches reference)
#pragma unroll
    for (int j = 0; j < 8; ++j) {
        int n0 = bn + wn * 64 + j * 8 + (lane & 3) * 2;
        __half hb0 = __float2half_rn(__ldg(bias + n0));
        __half hb1 = __float2half_rn(__ldg(bias + n0 + 1));
#pragma unroll
        for (int i = 0; i < 4; ++i) {
            int m0 = bm + wm * 64 + i * 16 + (lane >> 2);
            float2 v01, v23;
            v01.x = __half2float(__hadd(__float2half_rn(acc[i][j][0]), hb0));
            v01.y = __half2float(__hadd(__float2half_rn(acc[i][j][1]), hb1));
            v23.x = __half2float(__hadd(__float2half_rn(acc[i][j][2]), hb0));
            v23.y = __half2float(__hadd(__float2half_rn(acc[i][j][3]), hb1));
            *reinterpret_cast<float2*>(C + (size_t)m0 * N + n0) = v01;
            *reinterpret_cast<float2*>(C + (size_t)(m0 + 8) * N + n0) = v23;
        }
    }
}

// ------------------------------- launch --------------------------------------
// Identify inputs by element count (robust to metadata ordering):
// |bias|=N < |qzeros|=G*N/8 < |scales|=G*N < |qweight|=K*N/8 < |x|=M*K.
extern "C" void kernel_launch(void* const* d_in, const int* in_sizes, int n_in,
                              void* d_out, int out_size) {
    int order[5] = {0, 1, 2, 3, 4};
    for (int i = 0; i < 5; ++i)
        for (int j = i + 1; j < 5; ++j)
            if ((long long)in_sizes[order[j]] < (long long)in_sizes[order[i]]) {
                int t = order[i]; order[i] = order[j]; order[j] = t;
            }
    const float* bias   = (const float*)d_in[order[0]];   // N
    const int*   qz     = (const int*)  d_in[order[1]];    // G*N/8
    const float* scales = (const float*)d_in[order[2]];    // G*N
    const int*   qw     = (const int*)  d_in[order[3]];    // K*N/8
    const float* x      = (const float*)d_in[order[4]];    // M*K
    float*       out    = (float*)d_out;

    const int N = in_sizes[order[0]];                              // 12288
    const int K = (int)(((long long)in_sizes[order[3]] * 8) / N);  // 4096
    const int M = (int)((long long)in_sizes[order[4]] / K);        // 8192

    // 1) fused prepass: x f32->f16 + dequant int4 -> fp16 [K,N]
    {
        long long xcnt8 = (long long)M * K / 8;                // 8-float units
        int xb = (int)((xcnt8 + 255) / 256);
        long long dq = (long long)K * (N >> 3);
        int db = (int)((dq + 255) / 256);
        prep_kernel<<<xb + db, 256>>>(x, xcnt8, qw, qz, scales, K, N, xb);
    }
    // 2) GEMM
    {
        const int smem_bytes = (STG * BM * AST + STG * BK * BST) * (int)sizeof(__half);
        cudaFuncSetAttribute(gemm_hmma,
                             cudaFuncAttributeMaxDynamicSharedMemorySize, smem_bytes);
        dim3 grid(N / BN, M / BM);
        gemm_hmma<<<grid, 384, smem_bytes>>>(bias, out, M, N, K);
    }
}

// round 15
// speedup vs baseline: 1.1861x; 1.1861x over previous
#include <cuda_runtime.h>
#include <cuda_fp16.h>
#include <cstdint>

// ----------------------------------------------------------------------------
// WQLinearGEMM: out[M,N] = x[M,K] @ dequant(qweight,qzeros,scales)[K,N] + bias
// Round 15: R10 base (384 thr, 12 warps 2Mx6N, warp tile 64x64, BK=64, STG=3)
// + B-fragment software pipeline inside each ks (b double-buffered in 2x4 regs,
// prefetch b[jj+1] before jj's MMAs). Registers DROP by 8 vs R10.
// Fused prepass unchanged.
// ----------------------------------------------------------------------------

#define BM 128
#define BN 384
#define BK 64
#define STG 3
#define AST 72    // A smem row stride (halves): banks step 4/row, conflict-free
#define BST 392   // B smem row stride (halves): banks step 4/row, conflict-free

// static scratch: x fp16 (64MB), W fp16 (96MB)
static __device__ __half g_xh[8192UL * 4096UL];
static __device__ __half g_wdeq[4096UL * 12288UL];

// ------------------------------ helpers -------------------------------------
__device__ __forceinline__ uint32_t smem_u32(const void* p) {
    return (uint32_t)__cvta_generic_to_shared(p);
}
__device__ __forceinline__ void cpa16(uint32_t dst, const void* src) {
    asm volatile("cp.async.cg.shared.global [%0], [%1], 16;\n" :: "r"(dst), "l"(src));
}
__device__ __forceinline__ void cp_commit() {
    asm volatile("cp.async.commit_group;\n");
}
template <int NREM>
__device__ __forceinline__ void cp_wait() {
    asm volatile("cp.async.wait_group %0;\n" :: "n"(NREM));
}
__device__ __forceinline__ void st_cs_v4(void* p, uint4 v) {
    asm volatile("st.global.cs.v4.u32 [%0], {%1,%2,%3,%4};"
                 :: "l"(p), "r"(v.x), "r"(v.y), "r"(v.z), "r"(v.w) : "memory");
}

// ------------------- fused prepass: x f32->f16 + dequant ---------------------
__global__ void prep_kernel(const float* __restrict__ x, long long xcnt8,
                            const int* __restrict__ qw,
                            const int* __restrict__ qz,
                            const float* __restrict__ scales,
                            int K, int N, int xb) {
    if ((int)blockIdx.x < xb) {
        long long i = (long long)blockIdx.x * blockDim.x + threadIdx.x;
        if (i >= xcnt8) return;
        const float4* src = reinterpret_cast<const float4*>(x) + i * 2;
        float4 v0 = src[0];
        float4 v1 = src[1];
        __half2 a = __floats2half2_rn(v0.x, v0.y);
        __half2 b = __floats2half2_rn(v0.z, v0.w);
        __half2 c = __floats2half2_rn(v1.x, v1.y);
        __half2 d = __floats2half2_rn(v1.z, v1.w);
        uint4 u;
        u.x = *reinterpret_cast<const uint32_t*>(&a);
        u.y = *reinterpret_cast<const uint32_t*>(&b);
        u.z = *reinterpret_cast<const uint32_t*>(&c);
        u.w = *reinterpret_cast<const uint32_t*>(&d);
        st_cs_v4(reinterpret_cast<uint4*>(g_xh) + i, u);
    } else {
        const int N8 = N >> 3;
        long long idx = (long long)(blockIdx.x - xb) * blockDim.x + threadIdx.x;
        if (idx >= (long long)K * N8) return;
        int k  = (int)(idx / N8);
        int n8 = (int)(idx - (long long)k * N8);
        int g  = k >> 7;  // GROUP_SIZE = 128

        unsigned u = (unsigned)qw[idx];
        unsigned z = (unsigned)qz[(size_t)g * N8 + n8];
        float4 s0 = *reinterpret_cast<const float4*>(scales + (size_t)g * N + n8 * 8);
        float4 s1 = *reinterpret_cast<const float4*>(scales + (size_t)g * N + n8 * 8 + 4);
        float s[8] = {s0.x, s0.y, s0.z, s0.w, s1.x, s1.y, s1.z, s1.w};

        __half outv[8];
#pragma unroll
        for (int j = 0; j < 8; ++j) {
            // output element j comes from nibble {0,4,1,5,2,6,3,7}[j]
            const int sh = (j & 1) ? (16 + (j >> 1) * 4) : ((j >> 1) * 4);
            int wq = (u >> sh) & 15;
            int zq = (z >> sh) & 15;
            outv[j] = __float2half_rn((float)(wq - zq) * s[j]);
        }
        st_cs_v4(g_wdeq + (size_t)k * N + n8 * 8,
                 *reinterpret_cast<const uint4*>(outv));
    }
}

// ------------------------------- GEMM kernel --------------------------------
// 384 threads, 12 warps (2M x 6N), warp tile 64x64 via m16n8k16.
__global__ __launch_bounds__(384, 1)
void gemm_hmma(const float* __restrict__ bias, float* __restrict__ C,
               int M, int N, int K) {
    extern __shared__ __half sm[];
    __half* As = sm;                       // [STG][BM][AST]
    __half* Bs = sm + STG * BM * AST;      // [STG][BK][BST]

    const int tid  = threadIdx.x;
    const int lane = tid & 31;
    const int warp = tid >> 5;
    const int wm = warp / 6;   // 0..1
    const int wn = warp % 6;   // 0..5

    const int bm = blockIdx.y * BM;
    const int bn = blockIdx.x * BN;
    const int KT = K / BK;

    const __half* Ag = g_xh   + (size_t)bm * K;
    const __half* Bg = g_wdeq + (size_t)bn;

    float acc[4][8][4];
#pragma unroll
    for (int i = 0; i < 4; ++i)
#pragma unroll
        for (int j = 0; j < 8; ++j)
#pragma unroll
            for (int r = 0; r < 4; ++r) acc[i][j][r] = 0.0f;

    // cp.async coords: A handled by threads 0..255 (4 chunks), B by all (8 chunks)
    const int ar = tid >> 3;            // A row (0..31 for tid<256), +32*it
    const int ac = (tid & 7) * 8;       // A col
    const int br = tid / 48;            // B row (0..7), +8*it
    const int bc = (tid % 48) * 8;      // B col (0..376)

    auto load_stage = [&](int s, int kt) {
        if (tid < 256) {
            const __half* Asrc = Ag + kt * BK;
            uint32_t ad = smem_u32(As + s * BM * AST);
#pragma unroll
            for (int it = 0; it < 4; ++it) {
                int r = ar + it * 32;
                cpa16(ad + (r * AST + ac) * 2, Asrc + (size_t)r * K + ac);
            }
        }
        const __half* Bsrc = Bg + (size_t)(kt * BK) * N;
        uint32_t bd = smem_u32(Bs + s * BK * BST);
#pragma unroll
        for (int it = 0; it < 8; ++it) {
            int r = br + it * 8;
            cpa16(bd + (r * BST + bc) * 2, Bsrc + (size_t)r * N + bc);
        }
    };

    // fragment ldmatrix coords (hoisted)
    const int a_row_base = wm * 64 + (lane & 15);
    const int a_col_lane = (lane >> 4) * 8;
    const int b_row_lane = lane & 15;
    const int b_col_base = wn * 64 + (lane >> 4) * 8;

    // prologue: stages 0..STG-2
#pragma unroll
    for (int p = 0; p < STG - 1; ++p) {
        load_stage(p, p);
        cp_commit();
    }

#pragma unroll 1
    for (int kt = 0; kt < KT; ++kt) {
        cp_wait<STG - 2>();
        __syncthreads();
        int nk = kt + STG - 1;
        if (nk < KT) load_stage(nk % STG, nk);
        cp_commit();

        const int s = kt % STG;
        uint32_t abase = smem_u32(As + s * BM * AST);
        uint32_t bbase = smem_u32(Bs + s * BK * BST);

#pragma unroll
        for (int ks = 0; ks < BK / 16; ++ks) {
            uint32_t a[4][4];
            uint32_t b[2][4];   // double-buffered B fragment (per jj)

            // b0 first (its latency hides under the A ldmatrix issues)
            {
                int row = ks * 16 + b_row_lane;
                int col = b_col_base;
                asm volatile(
                    "ldmatrix.sync.aligned.m8n8.x4.trans.shared.b16 {%0,%1,%2,%3}, [%4];"
                    : "=r"(b[0][0]), "=r"(b[0][1]), "=r"(b[0][2]), "=r"(b[0][3])
                    : "r"(bbase + (row * BST + col) * 2));
            }
#pragma unroll
            for (int i = 0; i < 4; ++i) {
                int row = a_row_base + i * 16;
                int col = ks * 16 + a_col_lane;
                asm volatile(
                    "ldmatrix.sync.aligned.m8n8.x4.shared.b16 {%0,%1,%2,%3}, [%4];"
                    : "=r"(a[i][0]), "=r"(a[i][1]), "=r"(a[i][2]), "=r"(a[i][3])
                    : "r"(abase + (row * AST + col) * 2));
            }

#pragma unroll
            for (int jj = 0; jj < 4; ++jj) {
                // prefetch next jj's B fragment before this jj's MMAs
                if (jj < 3) {
                    int row = ks * 16 + b_row_lane;
                    int col = b_col_base + (jj + 1) * 16;
                    asm volatile(
                        "ldmatrix.sync.aligned.m8n8.x4.trans.shared.b16 {%0,%1,%2,%3}, [%4];"
                        : "=r"(b[(jj + 1) & 1][0]), "=r"(b[(jj + 1) & 1][1]),
                          "=r"(b[(jj + 1) & 1][2]), "=r"(b[(jj + 1) & 1][3])
                        : "r"(bbase + (row * BST + col) * 2));
                }
                const int fb = jj & 1;
#pragma unroll
                for (int i = 0; i < 4; ++i) {
                    asm volatile(
                        "mma.sync.aligned.m16n8k16.row.col.f32.f16.f16.f32 "
                        "{%0,%1,%2,%3}, {%4,%5,%6,%7}, {%8,%9}, {%0,%1,%2,%3};"
                        : "+f"(acc[i][jj * 2][0]), "+f"(acc[i][jj * 2][1]),
                          "+f"(acc[i][jj * 2][2]), "+f"(acc[i][jj * 2][3])
                        : "r"(a[i][0]), "r"(a[i][1]), "r"(a[i][2]), "r"(a[i][3]),
                          "r"(b[fb][0]), "r"(b[fb][1]));
                    asm volatile(
                        "mma.sync.aligned.m16n8k16.row.col.f32.f16.f16.f32 "
                        "{%0,%1,%2,%3}, {%4,%5,%6,%7}, {%8,%9}, {%0,%1,%2,%3};"
                        : "+f"(acc[i][jj * 2 + 1][0]), "+f"(acc[i][jj * 2 + 1][1]),
                          "+f"(acc[i][jj * 2 + 1][2]), "+f"(acc[i][jj * 2 + 1][3])
                        : "r"(a[i][0]), "r"(a[i][1]), "r"(a[i][2]), "r"(a[i][3]),
                          "r"(b[fb][2]), "r"(b[fb][3]));
                }
            }
        }
    }

    // epilogue: round acc to f16, add f16 bias, widen to f32 (matches reference)
#pragma unroll
    for (int j = 0; j < 8; ++j) {
        int n0 = bn + wn * 64 + j * 8 + (lane & 3) * 2;
        __half hb0 = __float2half_rn(__ldg(bias + n0));
        __half hb1 = __float2half_rn(__ldg(bias + n0 + 1));
#pragma unroll
        for (int i = 0; i < 4; ++i) {
            int m0 = bm + wm * 64 + i * 16 + (lane >> 2);
            float2 v01, v23;
            v01.x = __half2float(__hadd(__float2half_rn(acc[i][j][0]), hb0));
            v01.y = __half2float(__hadd(__float2half_rn(acc[i][j][1]), hb1));
            v23.x = __half2float(__hadd(__float2half_rn(acc[i][j][2]), hb0));
            v23.y = __half2float(__hadd(__float2half_rn(acc[i][j][3]), hb1));
            *reinterpret_cast<float2*>(C + (size_t)m0 * N + n0) = v01;
            *reinterpret_cast<float2*>(C + (size_t)(m0 + 8) * N + n0) = v23;
        }
    }
}

// ------------------------------- launch --------------------------------------
// Identify inputs by element count (robust to metadata ordering):
// |bias|=N < |qzeros|=G*N/8 < |scales|=G*N < |qweight|=K*N/8 < |x|=M*K.
extern "C" void kernel_launch(void* const* d_in, const int* in_sizes, int n_in,
                              void* d_out, int out_size) {
    int order[5] = {0, 1, 2, 3, 4};
    for (int i = 0; i < 5; ++i)
        for (int j = i + 1; j < 5; ++j)
            if ((long long)in_sizes[order[j]] < (long long)in_sizes[order[i]]) {
                int t = order[i]; order[i] = order[j]; order[j] = t;
            }
    const float* bias   = (const float*)d_in[order[0]];   // N
    const int*   qz     = (const int*)  d_in[order[1]];    // G*N/8
    const float* scales = (const float*)d_in[order[2]];    // G*N
    const int*   qw     = (const int*)  d_in[order[3]];    // K*N/8
    const float* x      = (const float*)d_in[order[4]];    // M*K
    float*       out    = (float*)d_out;

    const int N = in_sizes[order[0]];                              // 12288
    const int K = (int)(((long long)in_sizes[order[3]] * 8) / N);  // 4096
    const int M = (int)((long long)in_sizes[order[4]] / K);        // 8192

    // 1) fused prepass: x f32->f16 + dequant int4 -> fp16 [K,N]
    {
        long long xcnt8 = (long long)M * K / 8;                // 8-float units
        int xb = (int)((xcnt8 + 255) / 256);
        long long dq = (long long)K * (N >> 3);
        int db = (int)((dq + 255) / 256);
        prep_kernel<<<xb + db, 256>>>(x, xcnt8, qw, qz, scales, K, N, xb);
    }
    // 2) GEMM
    {
        const int smem_bytes = (STG * BM * AST + STG * BK * BST) * (int)sizeof(__half);
        cudaFuncSetAttribute(gemm_hmma,
                             cudaFuncAttributeMaxDynamicSharedMemorySize, smem_bytes);
        dim3 grid(N / BN, M / BM);
        gemm_hmma<<<grid, 384, smem_bytes>>>(bias, out, M, N, K);
    }
}

// round 16
// speedup vs baseline: 1.2225x; 1.0306x over previous
#include <cuda_runtime.h>
#include <cuda_fp16.h>
#include <cstdint>

// ----------------------------------------------------------------------------
// WQLinearGEMM: out[M,N] = x[M,K] @ dequant(qweight,qzeros,scales)[K,N] + bias
// Round 16: R15 + cross-ks b0 prefetch (at jj==3, load next ks's b0 into the
// dead b[0] slot). Zero extra registers; buffer rotation stays consistent.
// Base: 384 thr, 12 warps 2Mx6N, warp tile 64x64, BK=64, STG=3 cp.async.
// Fused prepass unchanged.
// ----------------------------------------------------------------------------

#define BM 128
#define BN 384
#define BK 64
#define STG 3
#define AST 72    // A smem row stride (halves): banks step 4/row, conflict-free
#define BST 392   // B smem row stride (halves): banks step 4/row, conflict-free

// static scratch: x fp16 (64MB), W fp16 (96MB)
static __device__ __half g_xh[8192UL * 4096UL];
static __device__ __half g_wdeq[4096UL * 12288UL];

// ------------------------------ helpers -------------------------------------
__device__ __forceinline__ uint32_t smem_u32(const void* p) {
    return (uint32_t)__cvta_generic_to_shared(p);
}
__device__ __forceinline__ void cpa16(uint32_t dst, const void* src) {
    asm volatile("cp.async.cg.shared.global [%0], [%1], 16;\n" :: "r"(dst), "l"(src));
}
__device__ __forceinline__ void cp_commit() {
    asm volatile("cp.async.commit_group;\n");
}
template <int NREM>
__device__ __forceinline__ void cp_wait() {
    asm volatile("cp.async.wait_group %0;\n" :: "n"(NREM));
}
__device__ __forceinline__ void st_cs_v4(void* p, uint4 v) {
    asm volatile("st.global.cs.v4.u32 [%0], {%1,%2,%3,%4};"
                 :: "l"(p), "r"(v.x), "r"(v.y), "r"(v.z), "r"(v.w) : "memory");
}

// ------------------- fused prepass: x f32->f16 + dequant ---------------------
__global__ void prep_kernel(const float* __restrict__ x, long long xcnt8,
                            const int* __restrict__ qw,
                            const int* __restrict__ qz,
                            const float* __restrict__ scales,
                            int K, int N, int xb) {
    if ((int)blockIdx.x < xb) {
        long long i = (long long)blockIdx.x * blockDim.x + threadIdx.x;
        if (i >= xcnt8) return;
        const float4* src = reinterpret_cast<const float4*>(x) + i * 2;
        float4 v0 = src[0];
        float4 v1 = src[1];
        __half2 a = __floats2half2_rn(v0.x, v0.y);
        __half2 b = __floats2half2_rn(v0.z, v0.w);
        __half2 c = __floats2half2_rn(v1.x, v1.y);
        __half2 d = __floats2half2_rn(v1.z, v1.w);
        uint4 u;
        u.x = *reinterpret_cast<const uint32_t*>(&a);
        u.y = *reinterpret_cast<const uint32_t*>(&b);
        u.z = *reinterpret_cast<const uint32_t*>(&c);
        u.w = *reinterpret_cast<const uint32_t*>(&d);
        st_cs_v4(reinterpret_cast<uint4*>(g_xh) + i, u);
    } else {
        const int N8 = N >> 3;
        long long idx = (long long)(blockIdx.x - xb) * blockDim.x + threadIdx.x;
        if (idx >= (long long)K * N8) return;
        int k  = (int)(idx / N8);
        int n8 = (int)(idx - (long long)k * N8);
        int g  = k >> 7;  // GROUP_SIZE = 128

        unsigned u = (unsigned)qw[idx];
        unsigned z = (unsigned)qz[(size_t)g * N8 + n8];
        float4 s0 = *reinterpret_cast<const float4*>(scales + (size_t)g * N + n8 * 8);
        float4 s1 = *reinterpret_cast<const float4*>(scales + (size_t)g * N + n8 * 8 + 4);
        float s[8] = {s0.x, s0.y, s0.z, s0.w, s1.x, s1.y, s1.z, s1.w};

        __half outv[8];
#pragma unroll
        for (int j = 0; j < 8; ++j) {
            // output element j comes from nibble {0,4,1,5,2,6,3,7}[j]
            const int sh = (j & 1) ? (16 + (j >> 1) * 4) : ((j >> 1) * 4);
            int wq = (u >> sh) & 15;
            int zq = (z >> sh) & 15;
            outv[j] = __float2half_rn((float)(wq - zq) * s[j]);
        }
        st_cs_v4(g_wdeq + (size_t)k * N + n8 * 8,
                 *reinterpret_cast<const uint4*>(outv));
    }
}

// ------------------------------- GEMM kernel --------------------------------
// 384 threads, 12 warps (2M x 6N), warp tile 64x64 via m16n8k16.
__global__ __launch_bounds__(384, 1)
void gemm_hmma(const float* __restrict__ bias, float* __restrict__ C,
               int M, int N, int K) {
    extern __shared__ __half sm[];
    __half* As = sm;                       // [STG][BM][AST]
    __half* Bs = sm + STG * BM * AST;      // [STG][BK][BST]

    const int tid  = threadIdx.x;
    const int lane = tid & 31;
    const int warp = tid >> 5;
    const int wm = warp / 6;   // 0..1
    const int wn = warp % 6;   // 0..5

    const int bm = blockIdx.y * BM;
    const int bn = blockIdx.x * BN;
    const int KT = K / BK;

    const __half* Ag = g_xh   + (size_t)bm * K;
    const __half* Bg = g_wdeq + (size_t)bn;

    float acc[4][8][4];
#pragma unroll
    for (int i = 0; i < 4; ++i)
#pragma unroll
        for (int j = 0; j < 8; ++j)
#pragma unroll
            for (int r = 0; r < 4; ++r) acc[i][j][r] = 0.0f;

    // cp.async coords: A handled by threads 0..255 (4 chunks), B by all (8 chunks)
    const int ar = tid >> 3;            // A row (0..31 for tid<256), +32*it
    const int ac = (tid & 7) * 8;       // A col
    const int br = tid / 48;            // B row (0..7), +8*it
    const int bc = (tid % 48) * 8;      // B col (0..376)

    auto load_stage = [&](int s, int kt) {
        if (tid < 256) {
            const __half* Asrc = Ag + kt * BK;
            uint32_t ad = smem_u32(As + s * BM * AST);
#pragma unroll
            for (int it = 0; it < 4; ++it) {
                int r = ar + it * 32;
                cpa16(ad + (r * AST + ac) * 2, Asrc + (size_t)r * K + ac);
            }
        }
        const __half* Bsrc = Bg + (size_t)(kt * BK) * N;
        uint32_t bd = smem_u32(Bs + s * BK * BST);
#pragma unroll
        for (int it = 0; it < 8; ++it) {
            int r = br + it * 8;
            cpa16(bd + (r * BST + bc) * 2, Bsrc + (size_t)r * N + bc);
        }
    };

    // fragment ldmatrix coords (hoisted)
    const int a_row_base = wm * 64 + (lane & 15);
    const int a_col_lane = (lane >> 4) * 8;
    const int b_row_lane = lane & 15;
    const int b_col_base = wn * 64 + (lane >> 4) * 8;

    // prologue: stages 0..STG-2
#pragma unroll
    for (int p = 0; p < STG - 1; ++p) {
        load_stage(p, p);
        cp_commit();
    }

#pragma unroll 1
    for (int kt = 0; kt < KT; ++kt) {
        cp_wait<STG - 2>();
        __syncthreads();
        int nk = kt + STG - 1;
        if (nk < KT) load_stage(nk % STG, nk);
        cp_commit();

        const int s = kt % STG;
        uint32_t abase = smem_u32(As + s * BM * AST);
        uint32_t bbase = smem_u32(Bs + s * BK * BST);

        uint32_t b[2][4];   // double-buffered B fragment, persists across ks

        // ks0's b0 (later ks get their b0 prefetched at previous ks's jj==3)
        {
            int row = b_row_lane;
            int col = b_col_base;
            asm volatile(
                "ldmatrix.sync.aligned.m8n8.x4.trans.shared.b16 {%0,%1,%2,%3}, [%4];"
                : "=r"(b[0][0]), "=r"(b[0][1]), "=r"(b[0][2]), "=r"(b[0][3])
                : "r"(bbase + (row * BST + col) * 2));
        }

#pragma unroll
        for (int ks = 0; ks < BK / 16; ++ks) {
            uint32_t a[4][4];
#pragma unroll
            for (int i = 0; i < 4; ++i) {
                int row = a_row_base + i * 16;
                int col = ks * 16 + a_col_lane;
                asm volatile(
                    "ldmatrix.sync.aligned.m8n8.x4.shared.b16 {%0,%1,%2,%3}, [%4];"
                    : "=r"(a[i][0]), "=r"(a[i][1]), "=r"(a[i][2]), "=r"(a[i][3])
                    : "r"(abase + (row * AST + col) * 2));
            }

#pragma unroll
            for (int jj = 0; jj < 4; ++jj) {
                if (jj < 3) {
                    // prefetch this ks's next B fragment
                    int row = ks * 16 + b_row_lane;
                    int col = b_col_base + (jj + 1) * 16;
                    asm volatile(
                        "ldmatrix.sync.aligned.m8n8.x4.trans.shared.b16 {%0,%1,%2,%3}, [%4];"
                        : "=r"(b[(jj + 1) & 1][0]), "=r"(b[(jj + 1) & 1][1]),
                          "=r"(b[(jj + 1) & 1][2]), "=r"(b[(jj + 1) & 1][3])
                        : "r"(bbase + (row * BST + col) * 2));
                } else if (ks < BK / 16 - 1) {
                    // cross-ks: prefetch next ks's b0 into the dead b[0] slot
                    int row = (ks + 1) * 16 + b_row_lane;
                    int col = b_col_base;
                    asm volatile(
                        "ldmatrix.sync.aligned.m8n8.x4.trans.shared.b16 {%0,%1,%2,%3}, [%4];"
                        : "=r"(b[0][0]), "=r"(b[0][1]), "=r"(b[0][2]), "=r"(b[0][3])
                        : "r"(bbase + (row * BST + col) * 2));
                }
                const int fb = jj & 1;
#pragma unroll
                for (int i = 0; i < 4; ++i) {
                    asm volatile(
                        "mma.sync.aligned.m16n8k16.row.col.f32.f16.f16.f32 "
                        "{%0,%1,%2,%3}, {%4,%5,%6,%7}, {%8,%9}, {%0,%1,%2,%3};"
                        : "+f"(acc[i][jj * 2][0]), "+f"(acc[i][jj * 2][1]),
                          "+f"(acc[i][jj * 2][2]), "+f"(acc[i][jj * 2][3])
                        : "r"(a[i][0]), "r"(a[i][1]), "r"(a[i][2]), "r"(a[i][3]),
                          "r"(b[fb][0]), "r"(b[fb][1]));
                    asm volatile(
                        "mma.sync.aligned.m16n8k16.row.col.f32.f16.f16.f32 "
                        "{%0,%1,%2,%3}, {%4,%5,%6,%7}, {%8,%9}, {%0,%1,%2,%3};"
                        : "+f"(acc[i][jj * 2 + 1][0]), "+f"(acc[i][jj * 2 + 1][1]),
                          "+f"(acc[i][jj * 2 + 1][2]), "+f"(acc[i][jj * 2 + 1][3])
                        : "r"(a[i][0]), "r"(a[i][1]), "r"(a[i][2]), "r"(a[i][3]),
                          "r"(b[fb][2]), "r"(b[fb][3]));
                }
            }
        }
    }

    // epilogue: round acc to f16, add f16 bias, widen to f32 (matches reference)
#pragma unroll
    for (int j = 0; j < 8; ++j) {
        int n0 = bn + wn * 64 + j * 8 + (lane & 3) * 2;
        __half hb0 = __float2half_rn(__ldg(bias + n0));
        __half hb1 = __float2half_rn(__ldg(bias + n0 + 1));
#pragma unroll
        for (int i = 0; i < 4; ++i) {
            int m0 = bm + wm * 64 + i * 16 + (lane >> 2);
            float2 v01, v23;
            v01.x = __half2float(__hadd(__float2half_rn(acc[i][j][0]), hb0));
            v01.y = __half2float(__hadd(__float2half_rn(acc[i][j][1]), hb1));
            v23.x = __half2float(__hadd(__float2half_rn(acc[i][j][2]), hb0));
            v23.y = __half2float(__hadd(__float2half_rn(acc[i][j][3]), hb1));
            *reinterpret_cast<float2*>(C + (size_t)m0 * N + n0) = v01;
            *reinterpret_cast<float2*>(C + (size_t)(m0 + 8) * N + n0) = v23;
        }
    }
}

// ------------------------------- launch --------------------------------------
// Identify inputs by element count (robust to metadata ordering):
// |bias|=N < |qzeros|=G*N/8 < |scales|=G*N < |qweight|=K*N/8 < |x|=M*K.
extern "C" void kernel_launch(void* const* d_in, const int* in_sizes, int n_in,
                              void* d_out, int out_size) {
    int order[5] = {0, 1, 2, 3, 4};
    for (int i = 0; i < 5; ++i)
        for (int j = i + 1; j < 5; ++j)
            if ((long long)in_sizes[order[j]] < (long long)in_sizes[order[i]]) {
                int t = order[i]; order[i] = order[j]; order[j] = t;
            }
    const float* bias   = (const float*)d_in[order[0]];   // N
    const int*   qz     = (const int*)  d_in[order[1]];    // G*N/8
    const float* scales = (const float*)d_in[order[2]];    // G*N
    const int*   qw     = (const int*)  d_in[order[3]];    // K*N/8
    const float* x      = (const float*)d_in[order[4]];    // M*K
    float*       out    = (float*)d_out;

    const int N = in_sizes[order[0]];                              // 12288
    const int K = (int)(((long long)in_sizes[order[3]] * 8) / N);  // 4096
    const int M = (int)((long long)in_sizes[order[4]] / K);        // 8192

    // 1) fused prepass: x f32->f16 + dequant int4 -> fp16 [K,N]
    {
        long long xcnt8 = (long long)M * K / 8;                // 8-float units
        int xb = (int)((xcnt8 + 255) / 256);
        long long dq = (long long)K * (N >> 3);
        int db = (int)((dq + 255) / 256);
        prep_kernel<<<xb + db, 256>>>(x, xcnt8, qw, qz, scales, K, N, xb);
    }
    // 2) GEMM
    {
        const int smem_bytes = (STG * BM * AST + STG * BK * BST) * (int)sizeof(__half);
        cudaFuncSetAttribute(gemm_hmma,
                             cudaFuncAttributeMaxDynamicSharedMemorySize, smem_bytes);
        dim3 grid(N / BN, M / BM);
        gemm_hmma<<<grid, 384, smem_bytes>>>(bias, out, M, N, K);
    }
}